// round 3
// baseline (speedup 1.0000x reference)
#include <cuda_runtime.h>
#include <cstdint>
#include <math.h>

// LSTM: B=64, T=512, I=256, H=1024, O=1
// gates = x_t @ W_ih^T + h @ W_hh^T + b_ih + b_hh   (fused, K = 256 + 1024)
// i,f,g,o gate order (PyTorch). out = tanh(h_T) @ fc_W^T + fc_b.

#define Bsz 64
#define Tsz 512
#define Isz 256
#define Hsz 1024
#define KC  32          // K-chunk size
#define HSTR 36         // h_s row stride (pad: conflict-free, 16B aligned)
#define WSTR 36         // w_s row stride
#define NXCH 8          // x chunks (256/32)
#define NCH  40         // total chunks (8 x + 32 h)

// Scratch state (static device globals: allocation-free per harness rules)
__device__ float g_h[2][Bsz * Hsz];   // ping-pong hidden state
__device__ float g_c[Bsz * Hsz];      // cell state (owner-exclusive)

__device__ __forceinline__ void cp16(uint32_t dst, const float* src) {
    asm volatile("cp.async.cg.shared.global [%0], [%1], 16;" :: "r"(dst), "l"(src));
}
__device__ __forceinline__ void cp_commit() {
    asm volatile("cp.async.commit_group;");
}
template <int N> __device__ __forceinline__ void cp_wait() {
    asm volatile("cp.async.wait_group %0;" :: "n"(N) : "memory");
}

__device__ __forceinline__ float sigmoidf_(float v) {
    return 1.0f / (1.0f + expf(-v));
}

// Grid: 128 blocks = 64 row-groups (16 h-indices, all 4 gates = 64 gate rows)
//                  x  2 batch-halves (32 batches each)
// Block: 128 threads, per-thread tile 4 batches x 4 rows, where the 4 rows are
// exactly gates {i,f,g,o} of h-index j = j0 + tr  ->  pointwise update in regs.
__global__ void __launch_bounds__(128, 1)
lstm_step_kernel(const float* __restrict__ x,
                 const float* __restrict__ Wih,
                 const float* __restrict__ Whh,
                 const float* __restrict__ bih,
                 const float* __restrict__ bhh,
                 int t)
{
    __shared__ float h_s[2][32 * HSTR];   //  4.6 KB x2 : h / x_t chunk [b][k]
    __shared__ float w_s[2][64 * WSTR];   //  9.2 KB x2 : W chunk [local row][k]

    const int tid = threadIdx.x;
    const int rg  = blockIdx.x & 63;      // row group
    const int bh  = blockIdx.x >> 6;      // batch half
    const int j0  = rg * 16;
    const int tb  = tid & 7;              // batch lane (0..7)
    const int tr  = tid >> 3;             // j within group (0..15)

    const float* __restrict__ hprev = g_h[t & 1];
    float*       __restrict__ hnext = g_h[(t + 1) & 1];

    uint32_t h_sm[2], w_sm[2];
    h_sm[0] = (uint32_t)__cvta_generic_to_shared(&h_s[0][0]);
    h_sm[1] = (uint32_t)__cvta_generic_to_shared(&h_s[1][0]);
    w_sm[0] = (uint32_t)__cvta_generic_to_shared(&w_s[0][0]);
    w_sm[1] = (uint32_t)__cvta_generic_to_shared(&w_s[1][0]);

    // Stage chunk c into buffer buf (cp.async, one commit group per chunk).
    auto issue = [&](int c, int buf) {
        const bool xpart = (c < NXCH);
        const int  kofs  = xpart ? c * KC : (c - NXCH) * KC;
        // h / x_t tile: 32 rows x 32 k  (256 x 16B)
        #pragma unroll
        for (int i = 0; i < 2; i++) {
            int idx = tid + i * 128;
            int bl  = idx >> 3;           // 0..31
            int q   = idx & 7;            // 16B quad within chunk
            int b   = bh * 32 + bl;
            const float* src = xpart
                ? (x + ((size_t)b * Tsz + t) * Isz + kofs + q * 4)
                : (hprev + (size_t)b * Hsz + kofs + q * 4);
            cp16(h_sm[buf] + (uint32_t)((bl * HSTR + q * 4) * 4), src);
        }
        // W tile: 64 rows x 32 k  (512 x 16B). Local row lr -> global row
        // R = gate*H + j0 + jj  with gate = lr>>4, jj = lr&15.
        #pragma unroll
        for (int i = 0; i < 4; i++) {
            int idx = tid + i * 128;
            int lr  = idx >> 3;           // 0..63
            int q   = idx & 7;
            int R   = (lr >> 4) * Hsz + j0 + (lr & 15);
            const float* src = xpart
                ? (Wih + (size_t)R * Isz + kofs + q * 4)
                : (Whh + (size_t)R * Hsz + kofs + q * 4);
            cp16(w_sm[buf] + (uint32_t)((lr * WSTR + q * 4) * 4), src);
        }
        cp_commit();
    };

    // acc[bb][gate]; init with biases (added exactly once per output)
    float acc[4][4];
    #pragma unroll
    for (int rr = 0; rr < 4; rr++) {
        int R = rr * Hsz + j0 + tr;
        float bsum = bih[R] + bhh[R];
        #pragma unroll
        for (int bb = 0; bb < 4; bb++) acc[bb][rr] = bsum;
    }

    issue(0, 0);

    for (int c = 0; c < NCH; c++) {
        if (c + 1 < NCH) {
            issue(c + 1, (c + 1) & 1);
            cp_wait<1>();                 // chunk c complete
        } else {
            cp_wait<0>();
        }
        __syncthreads();

        const float* hs = &h_s[c & 1][0];
        const float* ws = &w_s[c & 1][0];

        #pragma unroll
        for (int k = 0; k < KC; k += 4) {
            float4 wv[4], hv[4];
            #pragma unroll
            for (int rr = 0; rr < 4; rr++)
                wv[rr] = *(const float4*)(ws + (rr * 16 + tr) * WSTR + k);
            #pragma unroll
            for (int bb = 0; bb < 4; bb++)
                hv[bb] = *(const float4*)(hs + (bb * 8 + tb) * HSTR + k);
            #pragma unroll
            for (int bb = 0; bb < 4; bb++) {
                #pragma unroll
                for (int rr = 0; rr < 4; rr++) {
                    acc[bb][rr] = fmaf(hv[bb].x, wv[rr].x, acc[bb][rr]);
                    acc[bb][rr] = fmaf(hv[bb].y, wv[rr].y, acc[bb][rr]);
                    acc[bb][rr] = fmaf(hv[bb].z, wv[rr].z, acc[bb][rr]);
                    acc[bb][rr] = fmaf(hv[bb].w, wv[rr].w, acc[bb][rr]);
                }
            }
        }
        __syncthreads();                  // buffer reusable for chunk c+2
    }

    // Pointwise LSTM cell update — all 4 gates of (b, j) live in this thread.
    const int j = j0 + tr;
    #pragma unroll
    for (int bb = 0; bb < 4; bb++) {
        int b   = bh * 32 + bb * 8 + tb;
        int off = b * Hsz + j;
        float ig = sigmoidf_(acc[bb][0]);
        float fg = sigmoidf_(acc[bb][1]);
        float gg = tanhf(acc[bb][2]);
        float og = sigmoidf_(acc[bb][3]);
        float cn = fg * g_c[off] + ig * gg;
        g_c[off]   = cn;
        hnext[off] = og * tanhf(cn);
    }
}

__global__ void init_state_kernel() {
    int i = blockIdx.x * blockDim.x + threadIdx.x;
    if (i < Bsz * Hsz) {
        g_h[0][i] = 0.0f;
        g_c[i]    = 0.0f;
    }
}

// out[b] = fc_b[0] + sum_j tanh(h_T[b][j]) * fc_W[0][j]
__global__ void final_fc_kernel(const float* __restrict__ fcW,
                                const float* __restrict__ fcb,
                                float* __restrict__ out)
{
    const int b = blockIdx.x;
    const int tid = threadIdx.x;
    __shared__ float red[256];
    const float* h = g_h[0];              // T=512 even -> last h in buffer 0
    float s = 0.0f;
    for (int j = tid; j < Hsz; j += 256)
        s += tanhf(h[b * Hsz + j]) * fcW[j];
    red[tid] = s;
    __syncthreads();
    #pragma unroll
    for (int st = 128; st > 0; st >>= 1) {
        if (tid < st) red[tid] += red[tid + st];
        __syncthreads();
    }
    if (tid == 0) out[b] = red[0] + fcb[0];
}

extern "C" void kernel_launch(void* const* d_in, const int* in_sizes, int n_in,
                              void* d_out, int out_size)
{
    (void)in_sizes; (void)n_in; (void)out_size;
    const float* x   = (const float*)d_in[0];
    const float* Wih = (const float*)d_in[1];
    const float* Whh = (const float*)d_in[2];
    const float* bih = (const float*)d_in[3];
    const float* bhh = (const float*)d_in[4];
    const float* fcW = (const float*)d_in[5];
    const float* fcb = (const float*)d_in[6];
    float* out = (float*)d_out;

    init_state_kernel<<<(Bsz * Hsz + 255) / 256, 256>>>();
    for (int t = 0; t < Tsz; t++) {
        lstm_step_kernel<<<128, 128>>>(x, Wih, Whh, bih, bhh, t);
    }
    final_fc_kernel<<<Bsz, 256>>>(fcW, fcb, out);
}

// round 4
// speedup vs baseline: 1.0565x; 1.0565x over previous
#include <cuda_runtime.h>
#include <cstdint>
#include <math.h>

// LSTM: B=64, T=512, I=256, H=1024, O=1
// gates = x_t @ W_ih^T + h @ W_hh^T + b_ih + b_hh   (fused, K = 256 + 1024)
// i,f,g,o gate order (PyTorch). out = tanh(h_T) @ fc_W^T + fc_b.

#define Bsz 64
#define Tsz 512
#define Isz 256
#define Hsz 1024
#define KC  32          // K-chunk size
#define HSTR 36         // h_s row stride (pad: conflict-free, 16B aligned)
#define WSTR 36         // w_s row stride
#define NXCH 8          // x chunks (256/32)
#define NCH  40         // total chunks (8 x + 32 h)

// Scratch state (static device globals: allocation-free per harness rules)
__device__ float g_h[2][Bsz * Hsz];   // ping-pong hidden state
__device__ float g_c[Bsz * Hsz];      // cell state (owner-exclusive)

__device__ __forceinline__ void cp16(uint32_t dst, const float* src) {
    asm volatile("cp.async.cg.shared.global [%0], [%1], 16;" :: "r"(dst), "l"(src));
}
__device__ __forceinline__ void cp_commit() {
    asm volatile("cp.async.commit_group;");
}
template <int N> __device__ __forceinline__ void cp_wait() {
    asm volatile("cp.async.wait_group %0;" :: "n"(N) : "memory");
}

__device__ __forceinline__ float sigmoidf_(float v) {
    return 1.0f / (1.0f + expf(-v));
}

// Grid: 128 blocks = 64 row-groups (16 h-indices, all 4 gates = 64 gate rows)
//                  x  2 batch-halves (32 batches each)
// Block: 128 threads, per-thread tile 4 batches x 4 rows, where the 4 rows are
// exactly gates {i,f,g,o} of h-index j = j0 + tr  ->  pointwise update in regs.
__global__ void __launch_bounds__(128, 1)
lstm_step_kernel(const float* __restrict__ x,
                 const float* __restrict__ Wih,
                 const float* __restrict__ Whh,
                 const float* __restrict__ bih,
                 const float* __restrict__ bhh,
                 int t)
{
    __shared__ float h_s[2][32 * HSTR];   //  4.6 KB x2 : h / x_t chunk [b][k]
    __shared__ float w_s[2][64 * WSTR];   //  9.2 KB x2 : W chunk [local row][k]

    const int tid = threadIdx.x;
    const int rg  = blockIdx.x & 63;      // row group
    const int bh  = blockIdx.x >> 6;      // batch half
    const int j0  = rg * 16;
    const int tb  = tid & 7;              // batch lane (0..7)
    const int tr  = tid >> 3;             // j within group (0..15)

    const float* __restrict__ hprev = g_h[t & 1];
    float*       __restrict__ hnext = g_h[(t + 1) & 1];

    uint32_t h_sm[2], w_sm[2];
    h_sm[0] = (uint32_t)__cvta_generic_to_shared(&h_s[0][0]);
    h_sm[1] = (uint32_t)__cvta_generic_to_shared(&h_s[1][0]);
    w_sm[0] = (uint32_t)__cvta_generic_to_shared(&w_s[0][0]);
    w_sm[1] = (uint32_t)__cvta_generic_to_shared(&w_s[1][0]);

    // Stage chunk c into buffer buf (cp.async, one commit group per chunk).
    auto issue = [&](int c, int buf) {
        const bool xpart = (c < NXCH);
        const int  kofs  = xpart ? c * KC : (c - NXCH) * KC;
        // h / x_t tile: 32 rows x 32 k  (256 x 16B)
        #pragma unroll
        for (int i = 0; i < 2; i++) {
            int idx = tid + i * 128;
            int bl  = idx >> 3;           // 0..31
            int q   = idx & 7;            // 16B quad within chunk
            int b   = bh * 32 + bl;
            const float* src = xpart
                ? (x + ((size_t)b * Tsz + t) * Isz + kofs + q * 4)
                : (hprev + (size_t)b * Hsz + kofs + q * 4);
            cp16(h_sm[buf] + (uint32_t)((bl * HSTR + q * 4) * 4), src);
        }
        // W tile: 64 rows x 32 k  (512 x 16B). Local row lr -> global row
        // R = gate*H + j0 + jj  with gate = lr>>4, jj = lr&15.
        #pragma unroll
        for (int i = 0; i < 4; i++) {
            int idx = tid + i * 128;
            int lr  = idx >> 3;           // 0..63
            int q   = idx & 7;
            int R   = (lr >> 4) * Hsz + j0 + (lr & 15);
            const float* src = xpart
                ? (Wih + (size_t)R * Isz + kofs + q * 4)
                : (Whh + (size_t)R * Hsz + kofs + q * 4);
            cp16(w_sm[buf] + (uint32_t)((lr * WSTR + q * 4) * 4), src);
        }
        cp_commit();
    };

    // acc[bb][gate]; init with biases (added exactly once per output)
    float acc[4][4];
    #pragma unroll
    for (int rr = 0; rr < 4; rr++) {
        int R = rr * Hsz + j0 + tr;
        float bsum = bih[R] + bhh[R];
        #pragma unroll
        for (int bb = 0; bb < 4; bb++) acc[bb][rr] = bsum;
    }

    issue(0, 0);

    for (int c = 0; c < NCH; c++) {
        if (c + 1 < NCH) {
            issue(c + 1, (c + 1) & 1);
            cp_wait<1>();                 // chunk c complete
        } else {
            cp_wait<0>();
        }
        __syncthreads();

        const float* hs = &h_s[c & 1][0];
        const float* ws = &w_s[c & 1][0];

        #pragma unroll
        for (int k = 0; k < KC; k += 4) {
            float4 wv[4], hv[4];
            #pragma unroll
            for (int rr = 0; rr < 4; rr++)
                wv[rr] = *(const float4*)(ws + (rr * 16 + tr) * WSTR + k);
            #pragma unroll
            for (int bb = 0; bb < 4; bb++)
                hv[bb] = *(const float4*)(hs + (bb * 8 + tb) * HSTR + k);
            #pragma unroll
            for (int bb = 0; bb < 4; bb++) {
                #pragma unroll
                for (int rr = 0; rr < 4; rr++) {
                    acc[bb][rr] = fmaf(hv[bb].x, wv[rr].x, acc[bb][rr]);
                    acc[bb][rr] = fmaf(hv[bb].y, wv[rr].y, acc[bb][rr]);
                    acc[bb][rr] = fmaf(hv[bb].z, wv[rr].z, acc[bb][rr]);
                    acc[bb][rr] = fmaf(hv[bb].w, wv[rr].w, acc[bb][rr]);
                }
            }
        }
        __syncthreads();                  // buffer reusable for chunk c+2
    }

    // Pointwise LSTM cell update — all 4 gates of (b, j) live in this thread.
    const int j = j0 + tr;
    #pragma unroll
    for (int bb = 0; bb < 4; bb++) {
        int b   = bh * 32 + bb * 8 + tb;
        int off = b * Hsz + j;
        float ig = sigmoidf_(acc[bb][0]);
        float fg = sigmoidf_(acc[bb][1]);
        float gg = tanhf(acc[bb][2]);
        float og = sigmoidf_(acc[bb][3]);
        float cn = fg * g_c[off] + ig * gg;
        g_c[off]   = cn;
        hnext[off] = og * tanhf(cn);
    }
}

__global__ void init_state_kernel() {
    int i = blockIdx.x * blockDim.x + threadIdx.x;
    if (i < Bsz * Hsz) {
        g_h[0][i] = 0.0f;
        g_c[i]    = 0.0f;
    }
}

// out[b] = fc_b[0] + sum_j tanh(h_T[b][j]) * fc_W[0][j]
__global__ void final_fc_kernel(const float* __restrict__ fcW,
                                const float* __restrict__ fcb,
                                float* __restrict__ out)
{
    const int b = blockIdx.x;
    const int tid = threadIdx.x;
    __shared__ float red[256];
    const float* h = g_h[0];              // T=512 even -> last h in buffer 0
    float s = 0.0f;
    for (int j = tid; j < Hsz; j += 256)
        s += tanhf(h[b * Hsz + j]) * fcW[j];
    red[tid] = s;
    __syncthreads();
    #pragma unroll
    for (int st = 128; st > 0; st >>= 1) {
        if (tid < st) red[tid] += red[tid + st];
        __syncthreads();
    }
    if (tid == 0) out[b] = red[0] + fcb[0];
}

extern "C" void kernel_launch(void* const* d_in, const int* in_sizes, int n_in,
                              void* d_out, int out_size)
{
    (void)in_sizes; (void)n_in; (void)out_size;
    const float* x   = (const float*)d_in[0];
    const float* Wih = (const float*)d_in[1];
    const float* Whh = (const float*)d_in[2];
    const float* bih = (const float*)d_in[3];
    const float* bhh = (const float*)d_in[4];
    const float* fcW = (const float*)d_in[5];
    const float* fcb = (const float*)d_in[6];
    float* out = (float*)d_out;

    init_state_kernel<<<(Bsz * Hsz + 255) / 256, 256>>>();
    for (int t = 0; t < Tsz; t++) {
        lstm_step_kernel<<<128, 128>>>(x, Wih, Whh, bih, bhh, t);
    }
    final_fc_kernel<<<Bsz, 256>>>(fcW, fcb, out);
}

// round 7
// speedup vs baseline: 2.0016x; 1.8947x over previous
#include <cuda_runtime.h>
#include <cuda_bf16.h>
#include <cstdint>
#include <math.h>

// LSTM B=64, T=512, I=256, H=1024, O=1 — persistent mma.sync bf16-split kernel.
// Per step: gates[4096,64] = W_ext[4096,1280] @ act[1280,64], act=[x_t;h].
// 128 CTAs x (M=32 gate rows: 4 gates x 8 hidden units), N=64, K=1280.
// bf16 hi/lo split of both operands, 3-term MMA, fp32 accumulation.

#define NCTA 128
#define TPB  256
#define Tsz  512
#define Bsz  64
#define Isz  256
#define Hsz  1024
#define MROWS 32
#define KCH  64
#define NCHK 20
#define SA   72                     // padded smem row stride (bf16 elems)
#define ABYTES (MROWS * SA * 2)     // 4608
#define BBYTES (64 * SA * 2)        // 9216
#define AH   0
#define AL   ABYTES
#define BH   (2 * ABYTES)
#define BL   (2 * ABYTES + BBYTES)
#define BUFB (2 * ABYTES + 2 * BBYTES)   // 27648
#define EXST 66
#define EXCHOFF (4 * BUFB)
#define SMEM_DYN (4 * BUFB + MROWS * EXST * 4 + 64)

// ---------------- static device scratch (no allocation) ----------------
__device__ __align__(16) __nv_bfloat16 g_WrH[NCTA * MROWS * 1280];
__device__ __align__(16) __nv_bfloat16 g_WrL[NCTA * MROWS * 1280];
__device__ __align__(16) __nv_bfloat16 g_xh[(size_t)Bsz * Tsz * Isz];
__device__ __align__(16) __nv_bfloat16 g_xl[(size_t)Bsz * Tsz * Isz];
__device__ __align__(16) __nv_bfloat16 g_hh[2][Bsz * Hsz];
__device__ __align__(16) __nv_bfloat16 g_hl[2][Bsz * Hsz];
__device__ float    g_hf[Bsz * Hsz];
__device__ float    g_bsum[NCTA * MROWS];
__device__ unsigned g_cnt;

// ---------------- PTX helpers ----------------
__device__ __forceinline__ uint32_t smem_u32(const void* p) {
    uint32_t a;
    asm("{ .reg .u64 t; cvta.to.shared.u64 t, %1; cvt.u32.u64 %0, t; }" : "=r"(a) : "l"(p));
    return a;
}
__device__ __forceinline__ void cp16(uint32_t dst, const void* src) {
    asm volatile("cp.async.cg.shared.global [%0], [%1], 16;" :: "r"(dst), "l"(src));
}
#define CP_COMMIT() asm volatile("cp.async.commit_group;")
#define CP_WAIT(n)  asm volatile("cp.async.wait_group %0;" :: "n"(n) : "memory")

__device__ __forceinline__ void ldsm4(uint32_t* r, uint32_t a) {
    asm volatile("ldmatrix.sync.aligned.m8n8.x4.shared.b16 {%0,%1,%2,%3}, [%4];"
                 : "=r"(r[0]), "=r"(r[1]), "=r"(r[2]), "=r"(r[3]) : "r"(a));
}
__device__ __forceinline__ void mma16816(float* c, const uint32_t* a,
                                         uint32_t b0, uint32_t b1) {
    asm volatile(
        "mma.sync.aligned.m16n8k16.row.col.f32.bf16.bf16.f32 "
        "{%0,%1,%2,%3}, {%4,%5,%6,%7}, {%8,%9}, {%0,%1,%2,%3};"
        : "+f"(c[0]), "+f"(c[1]), "+f"(c[2]), "+f"(c[3])
        : "r"(a[0]), "r"(a[1]), "r"(a[2]), "r"(a[3]), "r"(b0), "r"(b1));
}

__device__ __forceinline__ float sigmoidf_(float v) { return 1.0f / (1.0f + expf(-v)); }

// ---------------- staging: one K-chunk into a ring buffer ----------------
__device__ __forceinline__ void stage_chunk(int tid, int cta, int t, int c, uint32_t buf) {
    // A: 32 rows x 64 k (hi+lo), 256 threads -> 1 position each
    {
        int row = tid >> 3, q = tid & 7;
        size_t so = (size_t)(cta * MROWS + row) * 1280 + c * KCH + q * 8;
        uint32_t d = (uint32_t)((row * SA + q * 8) * 2);
        cp16(buf + AH + d, g_WrH + so);
        cp16(buf + AL + d, g_WrL + so);
    }
    // B: 64 batches x 64 k (hi+lo)
    const int kofs = (c < 4) ? c * KCH : (c - 4) * KCH;
    #pragma unroll
    for (int i = 0; i < 2; i++) {
        int idx = tid + i * TPB;
        int b = idx >> 3, q = idx & 7;
        uint32_t d = (uint32_t)((b * SA + q * 8) * 2);
        const __nv_bfloat16 *sh, *sl;
        if (c < 4) {
            size_t o = ((size_t)b * Tsz + t) * Isz + kofs + q * 8;
            sh = g_xh + o; sl = g_xl + o;
        } else {
            size_t o = (size_t)b * Hsz + kofs + q * 8;
            sh = g_hh[t & 1] + o; sl = g_hl[t & 1] + o;
        }
        cp16(buf + BH + d, sh);
        cp16(buf + BL + d, sl);
    }
}

// ---------------- persistent LSTM kernel ----------------
__global__ void __launch_bounds__(TPB, 1) lstm_persist() {
    extern __shared__ __align__(16) char sm[];
    const uint32_t smu = smem_u32(sm);
    float* exch = (float*)(sm + EXCHOFF);

    const int tid = threadIdx.x;
    const int cta = blockIdx.x;
    const int w = tid >> 5, lane = tid & 31;
    const int m0 = (w & 1) * 16;
    const int n0 = (w >> 1) * 16;

    // ldmatrix per-lane bases (byte offsets within buffer region)
    const uint32_t aBase = (uint32_t)(((m0 + (lane & 15)) * SA + ((lane & 16) ? 8 : 0)) * 2);
    const uint32_t bBase = (uint32_t)(((n0 + (lane & 7) + ((lane & 16) ? 8 : 0)) * SA
                                      + ((lane & 8) ? 8 : 0)) * 2);

    // epilogue mapping: C frag rows er, er+8 / cols ecol within 16-wide n-slice
    const int er = m0 + (lane >> 2);
    const int ecol = 2 * (lane & 3);
    const float bias_a = g_bsum[cta * MROWS + er];
    const float bias_b = g_bsum[cta * MROWS + er + 8];

    // pointwise mapping: 2 cells/thread
    const int pb = tid & 63;
    const int pj0 = (tid >> 6) * 2;
    float c_reg[2] = {0.0f, 0.0f};

    for (int t = 0; t < Tsz; t++) {
        float acc[2][4];
        #pragma unroll
        for (int nt = 0; nt < 2; nt++)
            #pragma unroll
            for (int i = 0; i < 4; i++) acc[nt][i] = 0.0f;

        // prologue: stage chunks 0..2
        #pragma unroll
        for (int p = 0; p < 3; p++) {
            stage_chunk(tid, cta, t, p, smu + (uint32_t)(p * BUFB));
            CP_COMMIT();
        }

        for (int c = 0; c < NCHK; c++) {
            if (c + 3 < NCHK) {
                stage_chunk(tid, cta, t, c + 3, smu + (uint32_t)(((c + 3) & 3) * BUFB));
                CP_COMMIT();
                CP_WAIT(3);
            } else if (c == NCHK - 3) CP_WAIT(2);
            else if (c == NCHK - 2)   CP_WAIT(1);
            else                      CP_WAIT(0);
            __syncthreads();

            const uint32_t bufu = smu + (uint32_t)((c & 3) * BUFB);
            #pragma unroll
            for (int ks = 0; ks < 4; ks++) {
                const uint32_t ko = (uint32_t)(ks * 32);   // 16 elems * 2B
                uint32_t ah[4], al[4], bh[4], bl[4];
                ldsm4(ah, bufu + AH + aBase + ko);
                ldsm4(al, bufu + AL + aBase + ko);
                ldsm4(bh, bufu + BH + bBase + ko);
                ldsm4(bl, bufu + BL + bBase + ko);
                mma16816(acc[0], ah, bh[0], bh[1]);
                mma16816(acc[1], ah, bh[2], bh[3]);
                mma16816(acc[0], ah, bl[0], bl[1]);
                mma16816(acc[1], ah, bl[2], bl[3]);
                mma16816(acc[0], al, bh[0], bh[1]);
                mma16816(acc[1], al, bh[2], bh[3]);
            }
            __syncthreads();   // buffer (c&3) consumable for restage
        }

        // ---- gate exchange ----
        #pragma unroll
        for (int nt = 0; nt < 2; nt++) {
            int col = n0 + nt * 8 + ecol;
            exch[er * EXST + col]           = acc[nt][0] + bias_a;
            exch[er * EXST + col + 1]       = acc[nt][1] + bias_a;
            exch[(er + 8) * EXST + col]     = acc[nt][2] + bias_b;
            exch[(er + 8) * EXST + col + 1] = acc[nt][3] + bias_b;
        }
        __syncthreads();

        // ---- pointwise LSTM update (gate rows: i=0..7, f=8..15, g=16..23, o=24..31) ----
        __nv_bfloat16* hho = g_hh[(t + 1) & 1];
        __nv_bfloat16* hlo = g_hl[(t + 1) & 1];
        #pragma unroll
        for (int i = 0; i < 2; i++) {
            int jj = pj0 + i;
            float ig = sigmoidf_(exch[(0 * 8 + jj) * EXST + pb]);
            float fg = sigmoidf_(exch[(1 * 8 + jj) * EXST + pb]);
            float gg = tanhf    (exch[(2 * 8 + jj) * EXST + pb]);
            float og = sigmoidf_(exch[(3 * 8 + jj) * EXST + pb]);
            float cn = fg * c_reg[i] + ig * gg;
            c_reg[i] = cn;
            float hn = og * tanhf(cn);
            int off = pb * Hsz + cta * 8 + jj;
            __nv_bfloat16 hi = __float2bfloat16(hn);
            hho[off] = hi;
            hlo[off] = __float2bfloat16(hn - __bfloat162float(hi));
            if (t == Tsz - 1) g_hf[off] = hn;
        }

        // ---- grid barrier ----
        __threadfence();
        __syncthreads();
        if (tid == 0) {
            atomicAdd(&g_cnt, 1u);
            unsigned bound = (unsigned)(t + 1) * NCTA;
            while (*(volatile unsigned*)&g_cnt < bound) { }
            __threadfence();
        }
        __syncthreads();
    }
}

// ---------------- prep kernels ----------------
__global__ void reorder_w_kernel(const float* __restrict__ Wih,
                                 const float* __restrict__ Whh) {
    int idx = blockIdx.x * blockDim.x + threadIdx.x;
    if (idx >= NCTA * MROWS * 1280) return;
    int k  = idx % 1280;
    int rr = idx / 1280;
    int row = rr & (MROWS - 1), cta = rr >> 5;
    int gate = row >> 3, jj = row & 7;
    int R = gate * Hsz + cta * 8 + jj;
    float v = (k < Isz) ? Wih[(size_t)R * Isz + k]
                        : Whh[(size_t)R * Hsz + (k - Isz)];
    __nv_bfloat16 hi = __float2bfloat16(v);
    g_WrH[idx] = hi;
    g_WrL[idx] = __float2bfloat16(v - __bfloat162float(hi));
}

__global__ void split_x_kernel(const float* __restrict__ x) {
    size_t idx = (size_t)blockIdx.x * blockDim.x + threadIdx.x;
    if (idx >= (size_t)Bsz * Tsz * Isz) return;
    float v = x[idx];
    __nv_bfloat16 hi = __float2bfloat16(v);
    g_xh[idx] = hi;
    g_xl[idx] = __float2bfloat16(v - __bfloat162float(hi));
}

__global__ void bias_kernel(const float* __restrict__ bih,
                            const float* __restrict__ bhh) {
    int idx = blockIdx.x * blockDim.x + threadIdx.x;
    if (idx >= NCTA * MROWS) return;
    int row = idx & (MROWS - 1), cta = idx >> 5;
    int gate = row >> 3, jj = row & 7;
    int R = gate * Hsz + cta * 8 + jj;
    g_bsum[idx] = bih[R] + bhh[R];
}

__global__ void init_state_kernel() {
    int i = blockIdx.x * blockDim.x + threadIdx.x;
    if (i < Bsz * Hsz) {
        g_hh[0][i] = __float2bfloat16(0.0f);
        g_hl[0][i] = __float2bfloat16(0.0f);
    }
    if (i == 0) g_cnt = 0u;
}

__global__ void final_fc_kernel(const float* __restrict__ fcW,
                                const float* __restrict__ fcb,
                                float* __restrict__ out) {
    const int b = blockIdx.x;
    const int tid = threadIdx.x;
    __shared__ float red[256];
    float s = 0.0f;
    for (int j = tid; j < Hsz; j += 256)
        s += tanhf(g_hf[b * Hsz + j]) * fcW[j];
    red[tid] = s;
    __syncthreads();
    #pragma unroll
    for (int st = 128; st > 0; st >>= 1) {
        if (tid < st) red[tid] += red[tid + st];
        __syncthreads();
    }
    if (tid == 0) out[b] = red[0] + fcb[0];
}

extern "C" void kernel_launch(void* const* d_in, const int* in_sizes, int n_in,
                              void* d_out, int out_size)
{
    (void)in_sizes; (void)n_in; (void)out_size;
    const float* x   = (const float*)d_in[0];
    const float* Wih = (const float*)d_in[1];
    const float* Whh = (const float*)d_in[2];
    const float* bih = (const float*)d_in[3];
    const float* bhh = (const float*)d_in[4];
    const float* fcW = (const float*)d_in[5];
    const float* fcb = (const float*)d_in[6];
    float* out = (float*)d_out;

    cudaFuncSetAttribute(lstm_persist,
                         cudaFuncAttributeMaxDynamicSharedMemorySize, SMEM_DYN);

    init_state_kernel<<<(Bsz * Hsz + 255) / 256, 256>>>();
    reorder_w_kernel<<<(NCTA * MROWS * 1280 + 255) / 256, 256>>>(Wih, Whh);
    split_x_kernel<<<(int)(((size_t)Bsz * Tsz * Isz + 255) / 256), 256>>>(x);
    bias_kernel<<<(NCTA * MROWS + 255) / 256, 256>>>(bih, bhh);
    lstm_persist<<<NCTA, TPB, SMEM_DYN>>>();
    final_fc_kernel<<<Bsz, 256>>>(fcW, fcb, out);
}

// round 8
// speedup vs baseline: 2.0893x; 1.0438x over previous
#include <cuda_runtime.h>
#include <cuda_bf16.h>
#include <cstdint>
#include <math.h>

// LSTM B=64, T=512, I=256, H=1024, O=1 — persistent mma.sync kernel, W resident in smem.
// Per step: gates[4096,64] = W_ext[4096,1280] @ act[1280,64], act=[x_t;h].
// 128 CTAs x (M=32 reordered gate rows), N=64, K=1280 (20 chunks of 64).
// bf16 hi/lo split of both operands, 3-term MMA, fp32 accumulation.
// Warps: kg = w>>2 (chunk parity), within kg: m0=(w&1)*16, n0=((w>>1)&1)*32.

#define NCTA 128
#define TPB  256
#define Tsz  512
#define Bsz  64
#define Isz  256
#define Hsz  1024
#define NCHK 20
#define SA   72                         // padded row stride (bf16 elems) = 144B
#define ACH  9216                       // per-chunk A tile bytes (hi 4608 + lo 4608)
#define AHALF 4608
#define ABYTES (NCHK * ACH)             // 184320 — W resident
#define BBUF  18432                     // per B buffer (hi 9216 + lo 9216)
#define BLHALF 9216
#define BOFF  ABYTES
#define SMEM_DYN (ABYTES + 2 * BBUF)    // 221184
#define EXST 66

// ---------------- static device scratch (no allocation) ----------------
__device__ __align__(16) __nv_bfloat16 g_WrH[NCTA * 32 * 1280];
__device__ __align__(16) __nv_bfloat16 g_WrL[NCTA * 32 * 1280];
__device__ __align__(16) __nv_bfloat16 g_xh[(size_t)Bsz * Tsz * Isz];
__device__ __align__(16) __nv_bfloat16 g_xl[(size_t)Bsz * Tsz * Isz];
__device__ __align__(16) __nv_bfloat16 g_hh[2][Bsz * Hsz];
__device__ __align__(16) __nv_bfloat16 g_hl[2][Bsz * Hsz];
__device__ float    g_hf[Bsz * Hsz];
__device__ float    g_bsum[NCTA * 32];
__device__ unsigned g_cnt;

// ---------------- PTX helpers ----------------
__device__ __forceinline__ uint32_t smem_u32(const void* p) {
    uint32_t a;
    asm("{ .reg .u64 t; cvta.to.shared.u64 t, %1; cvt.u32.u64 %0, t; }" : "=r"(a) : "l"(p));
    return a;
}
__device__ __forceinline__ void cp16(uint32_t dst, const void* src) {
    asm volatile("cp.async.cg.shared.global [%0], [%1], 16;" :: "r"(dst), "l"(src));
}
#define CP_COMMIT() asm volatile("cp.async.commit_group;")
#define CP_WAIT(n)  asm volatile("cp.async.wait_group %0;" :: "n"(n) : "memory")

__device__ __forceinline__ void ldsm4(uint32_t* r, uint32_t a) {
    asm volatile("ldmatrix.sync.aligned.m8n8.x4.shared.b16 {%0,%1,%2,%3}, [%4];"
                 : "=r"(r[0]), "=r"(r[1]), "=r"(r[2]), "=r"(r[3]) : "r"(a));
}
__device__ __forceinline__ void mma16816(float* c, const uint32_t* a,
                                         uint32_t b0, uint32_t b1) {
    asm volatile(
        "mma.sync.aligned.m16n8k16.row.col.f32.bf16.bf16.f32 "
        "{%0,%1,%2,%3}, {%4,%5,%6,%7}, {%8,%9}, {%0,%1,%2,%3};"
        : "+f"(c[0]), "+f"(c[1]), "+f"(c[2]), "+f"(c[3])
        : "r"(a[0]), "r"(a[1]), "r"(a[2]), "r"(a[3]), "r"(b0), "r"(b1));
}

__device__ __forceinline__ float sigmoidf_(float v) { return 1.0f / (1.0f + expf(-v)); }

// ---------------- staging: one B K-chunk (act hi/lo) into a ring buffer ----------------
__device__ __forceinline__ void stage_b(int tid, int t, int c, uint32_t buf) {
    #pragma unroll
    for (int i = 0; i < 2; i++) {
        int idx = tid + i * TPB;          // 0..511
        int b = idx >> 3, q = idx & 7;
        uint32_t d = (uint32_t)(b * (SA * 2) + q * 16);
        const __nv_bfloat16 *sh, *sl;
        if (c < 4) {
            size_t o = ((size_t)b * Tsz + t) * Isz + c * 64 + q * 8;
            sh = g_xh + o; sl = g_xl + o;
        } else {
            size_t o = (size_t)b * Hsz + (c - 4) * 64 + q * 8;
            sh = g_hh[t & 1] + o; sl = g_hl[t & 1] + o;
        }
        cp16(buf + d, sh);
        cp16(buf + BLHALF + d, sl);
    }
}

// ---------------- persistent LSTM kernel (final FC folded in) ----------------
__global__ void __launch_bounds__(TPB, 1)
lstm_persist(const float* __restrict__ fcW, const float* __restrict__ fcb,
             float* __restrict__ out)
{
    extern __shared__ __align__(16) char sm[];
    const uint32_t smu = smem_u32(sm);
    float* exch = (float*)(sm + BOFF);     // aliases B ring (post-loop only)

    const int tid = threadIdx.x;
    const int cta = blockIdx.x;
    const int w = tid >> 5, lane = tid & 31;
    const int kg = w >> 2;                       // chunk parity group
    const int m0 = (w & 1) * 16;
    const int n0 = ((w >> 1) & 1) * 32;

    // ldmatrix lane bases (byte offsets inside a tile region)
    const uint32_t aBase = (uint32_t)(((m0 + (lane & 15)) * SA + ((lane & 16) ? 8 : 0)) * 2);
    const uint32_t bBase = (uint32_t)(((n0 + (lane & 7) + ((lane & 16) ? 8 : 0)) * SA
                                      + ((lane & 8) ? 8 : 0)) * 2);

    // epilogue frag mapping
    const int er = m0 + (lane >> 2);
    const int ecol = 2 * (lane & 3);

    // pointwise mapping: 2 cells (pb, pj0..pj0+1)
    const int pb = tid & 63;
    const int pj0 = (tid >> 6) * 2;
    float bias_pw[2][4];
    #pragma unroll
    for (int i = 0; i < 2; i++)
        #pragma unroll
        for (int g = 0; g < 4; g++)
            bias_pw[i][g] = g_bsum[cta * 32 + g * 8 + pj0 + i];
    float c_reg[2] = {0.0f, 0.0f};

    // ---- stage resident W (A operand) once: 10240 cp16 / 256 thr = 40 each ----
    {
        const __nv_bfloat16* wh = g_WrH + (size_t)cta * 32 * 1280;
        const __nv_bfloat16* wl = g_WrL + (size_t)cta * 32 * 1280;
        #pragma unroll
        for (int i = 0; i < 40; i++) {
            int idx = tid + i * TPB;         // 0..10239
            int c   = idx >> 9;              // chunk 0..19
            int rem = idx & 511;
            int half = rem >> 8;
            int row = (rem >> 3) & 31;
            int q   = rem & 7;
            size_t so = (size_t)row * 1280 + c * 64 + q * 8;
            uint32_t d = smu + (uint32_t)(c * ACH + half * AHALF + row * (SA * 2) + q * 16);
            cp16(d, (half ? wl : wh) + so);
        }
        CP_COMMIT();
    }

    for (int t = 0; t < Tsz; t++) {
        float acc[4][4];
        #pragma unroll
        for (int nt = 0; nt < 4; nt++)
            #pragma unroll
            for (int i = 0; i < 4; i++) acc[nt][i] = 0.0f;

        stage_b(tid, t, 0, smu + BOFF);
        CP_COMMIT();

        for (int c = 0; c < NCHK; c++) {
            if (c + 1 < NCHK) {
                stage_b(tid, t, c + 1, smu + BOFF + (uint32_t)(((c + 1) & 1) * BBUF));
                CP_COMMIT();
                CP_WAIT(1);
            } else {
                CP_WAIT(0);
            }
            __syncthreads();

            if ((c & 1) == kg) {
                const uint32_t at = smu + (uint32_t)(c * ACH);
                const uint32_t bt = smu + BOFF + (uint32_t)((c & 1) * BBUF);
                #pragma unroll
                for (int ks = 0; ks < 4; ks++) {
                    const uint32_t ko = (uint32_t)(ks * 32);
                    uint32_t ah[4], al[4], bh0[4], bh1[4], bl0[4], bl1[4];
                    ldsm4(ah,  at + aBase + ko);
                    ldsm4(al,  at + AHALF + aBase + ko);
                    ldsm4(bh0, bt + bBase + ko);
                    ldsm4(bh1, bt + 16 * (SA * 2) + bBase + ko);
                    ldsm4(bl0, bt + BLHALF + bBase + ko);
                    ldsm4(bl1, bt + BLHALF + 16 * (SA * 2) + bBase + ko);
                    mma16816(acc[0], ah, bh0[0], bh0[1]);
                    mma16816(acc[1], ah, bh0[2], bh0[3]);
                    mma16816(acc[2], ah, bh1[0], bh1[1]);
                    mma16816(acc[3], ah, bh1[2], bh1[3]);
                    mma16816(acc[0], ah, bl0[0], bl0[1]);
                    mma16816(acc[1], ah, bl0[2], bl0[3]);
                    mma16816(acc[2], ah, bl1[0], bl1[1]);
                    mma16816(acc[3], ah, bl1[2], bl1[3]);
                    mma16816(acc[0], al, bh0[0], bh0[1]);
                    mma16816(acc[1], al, bh0[2], bh0[3]);
                    mma16816(acc[2], al, bh1[0], bh1[1]);
                    mma16816(acc[3], al, bh1[2], bh1[3]);
                }
            }
            __syncthreads();
        }

        // ---- exchange: each kg writes its partial region ----
        {
            float* ex = exch + kg * (32 * EXST);
            #pragma unroll
            for (int nt = 0; nt < 4; nt++) {
                int col = n0 + nt * 8 + ecol;
                ex[er * EXST + col]           = acc[nt][0];
                ex[er * EXST + col + 1]       = acc[nt][1];
                ex[(er + 8) * EXST + col]     = acc[nt][2];
                ex[(er + 8) * EXST + col + 1] = acc[nt][3];
            }
        }
        __syncthreads();

        // ---- pointwise LSTM update ----
        __nv_bfloat16* hho = g_hh[(t + 1) & 1];
        __nv_bfloat16* hlo = g_hl[(t + 1) & 1];
        #pragma unroll
        for (int i = 0; i < 2; i++) {
            int jj = pj0 + i;
            float gv[4];
            #pragma unroll
            for (int g = 0; g < 4; g++) {
                int row = g * 8 + jj;
                gv[g] = exch[row * EXST + pb] + exch[32 * EXST + row * EXST + pb]
                        + bias_pw[i][g];
            }
            float ig = sigmoidf_(gv[0]);
            float fg = sigmoidf_(gv[1]);
            float gg = tanhf(gv[2]);
            float og = sigmoidf_(gv[3]);
            float cn = fg * c_reg[i] + ig * gg;
            c_reg[i] = cn;
            float hn = og * tanhf(cn);
            int off = pb * Hsz + cta * 8 + jj;
            __nv_bfloat16 hi = __float2bfloat16(hn);
            hho[off] = hi;
            hlo[off] = __float2bfloat16(hn - __bfloat162float(hi));
            if (t == Tsz - 1) g_hf[off] = hn;
        }

        // ---- grid barrier ----
        __threadfence();
        __syncthreads();
        if (tid == 0) {
            atomicAdd(&g_cnt, 1u);
            unsigned bound = (unsigned)(t + 1) * NCTA;
            while (*(volatile unsigned*)&g_cnt < bound) { }
            __threadfence();
        }
        __syncthreads();
    }

    // ---- final FC folded in: CTA b < 64 computes out[b] ----
    if (cta < Bsz) {
        float s = 0.0f;
        for (int j = tid; j < Hsz; j += TPB)
            s += tanhf(g_hf[cta * Hsz + j]) * fcW[j];
        #pragma unroll
        for (int d = 16; d > 0; d >>= 1)
            s += __shfl_xor_sync(0xFFFFFFFFu, s, d);
        __shared__ float red[8];
        if (lane == 0) red[w] = s;
        __syncthreads();
        if (tid == 0) {
            float tot = 0.0f;
            #pragma unroll
            for (int i = 0; i < 8; i++) tot += red[i];
            out[cta] = tot + fcb[0];
        }
    }
}

// ---------------- fused prep kernel ----------------
#define PREP_W_BLKS 20480            // 128*32*1280 / 256
#define PREP_X_BLKS 32768            // 64*512*256 / 256
#define PREP_B_BLKS 16               // 4096 / 256
#define PREP_I_BLKS 256              // 65536 / 256
#define PREP_GRID (PREP_W_BLKS + PREP_X_BLKS + PREP_B_BLKS + PREP_I_BLKS)

__global__ void prep_kernel(const float* __restrict__ x,
                            const float* __restrict__ Wih,
                            const float* __restrict__ Whh,
                            const float* __restrict__ bih,
                            const float* __restrict__ bhh)
{
    int bid = blockIdx.x;
    int tid = threadIdx.x;
    if (bid < PREP_W_BLKS) {
        int idx = bid * 256 + tid;                  // < 5,242,880
        int k  = idx % 1280;
        int rr = idx / 1280;
        int row = rr & 31, cta = rr >> 5;
        int gate = row >> 3, jj = row & 7;
        int R = gate * Hsz + cta * 8 + jj;
        float v = (k < Isz) ? Wih[(size_t)R * Isz + k]
                            : Whh[(size_t)R * Hsz + (k - Isz)];
        __nv_bfloat16 hi = __float2bfloat16(v);
        g_WrH[idx] = hi;
        g_WrL[idx] = __float2bfloat16(v - __bfloat162float(hi));
    } else if (bid < PREP_W_BLKS + PREP_X_BLKS) {
        size_t idx = (size_t)(bid - PREP_W_BLKS) * 256 + tid;   // < 8,388,608
        float v = x[idx];
        __nv_bfloat16 hi = __float2bfloat16(v);
        g_xh[idx] = hi;
        g_xl[idx] = __float2bfloat16(v - __bfloat162float(hi));
    } else if (bid < PREP_W_BLKS + PREP_X_BLKS + PREP_B_BLKS) {
        int idx = (bid - PREP_W_BLKS - PREP_X_BLKS) * 256 + tid;  // < 4096
        int row = idx & 31, cta = idx >> 5;
        int gate = row >> 3, jj = row & 7;
        int R = gate * Hsz + cta * 8 + jj;
        g_bsum[idx] = bih[R] + bhh[R];
    } else {
        int i = (bid - PREP_W_BLKS - PREP_X_BLKS - PREP_B_BLKS) * 256 + tid;  // < 65536
        g_hh[0][i] = __float2bfloat16(0.0f);
        g_hl[0][i] = __float2bfloat16(0.0f);
        if (i == 0) g_cnt = 0u;
    }
}

extern "C" void kernel_launch(void* const* d_in, const int* in_sizes, int n_in,
                              void* d_out, int out_size)
{
    (void)in_sizes; (void)n_in; (void)out_size;
    const float* x   = (const float*)d_in[0];
    const float* Wih = (const float*)d_in[1];
    const float* Whh = (const float*)d_in[2];
    const float* bih = (const float*)d_in[3];
    const float* bhh = (const float*)d_in[4];
    const float* fcW = (const float*)d_in[5];
    const float* fcb = (const float*)d_in[6];
    float* out = (float*)d_out;

    cudaFuncSetAttribute(lstm_persist,
                         cudaFuncAttributeMaxDynamicSharedMemorySize, SMEM_DYN);

    prep_kernel<<<PREP_GRID, 256>>>(x, Wih, Whh, bih, bhh);
    lstm_persist<<<NCTA, TPB, SMEM_DYN>>>(fcW, fcb, out);
}

// round 9
// speedup vs baseline: 2.3278x; 1.1142x over previous
#include <cuda_runtime.h>
#include <cuda_bf16.h>
#include <cstdint>
#include <math.h>

// LSTM B=64, T=512, I=256, H=1024, O=1 — persistent mma.sync kernel.
// W resident in smem (swizzled, 160KB); B (act) via 4-deep swizzled cp.async ring.
// gates[4096,64] = W_ext[4096,1280] @ act[1280,64]; 128 CTAs x M=32 rows.
// bf16 hi/lo split both operands, 3-term MMA, fp32 accum. One sync per chunk.

#define NCTA 128
#define TPB  256
#define Tsz  512
#define Bsz  64
#define Isz  256
#define Hsz  1024
#define NCHK 20
#define ACH   8192                      // per-chunk A bytes (hi 4096 + lo 4096)
#define AHALF 4096
#define ABYTES (NCHK * ACH)             // 163840 — W resident
#define BBUF  16384                     // per B buffer (hi 8192 + lo 8192)
#define BLHALF 8192
#define BOFF  ABYTES
#define SMEM_DYN (ABYTES + 4 * BBUF)    // 229376
#define EXST 66

// ---------------- static device scratch ----------------
__device__ __align__(16) __nv_bfloat16 g_WrH[NCTA * 32 * 1280];
__device__ __align__(16) __nv_bfloat16 g_WrL[NCTA * 32 * 1280];
__device__ __align__(16) __nv_bfloat16 g_xh[(size_t)Bsz * Tsz * Isz];
__device__ __align__(16) __nv_bfloat16 g_xl[(size_t)Bsz * Tsz * Isz];
__device__ __align__(16) __nv_bfloat16 g_hh[2][Bsz * Hsz];
__device__ __align__(16) __nv_bfloat16 g_hl[2][Bsz * Hsz];
__device__ float    g_hf[Bsz * Hsz];
__device__ float    g_bsum[NCTA * 32];
__device__ unsigned g_cnt;

// ---------------- PTX helpers ----------------
__device__ __forceinline__ uint32_t smem_u32(const void* p) {
    uint32_t a;
    asm("{ .reg .u64 t; cvta.to.shared.u64 t, %1; cvt.u32.u64 %0, t; }" : "=r"(a) : "l"(p));
    return a;
}
__device__ __forceinline__ void cp16(uint32_t dst, const void* src) {
    asm volatile("cp.async.cg.shared.global [%0], [%1], 16;" :: "r"(dst), "l"(src));
}
#define CP_COMMIT() asm volatile("cp.async.commit_group;")
#define CP_WAIT(n)  asm volatile("cp.async.wait_group %0;" :: "n"(n) : "memory")

__device__ __forceinline__ void ldsm4(uint32_t* r, uint32_t a) {
    asm volatile("ldmatrix.sync.aligned.m8n8.x4.shared.b16 {%0,%1,%2,%3}, [%4];"
                 : "=r"(r[0]), "=r"(r[1]), "=r"(r[2]), "=r"(r[3]) : "r"(a));
}
__device__ __forceinline__ void mma16816(float* c, const uint32_t* a,
                                         uint32_t b0, uint32_t b1) {
    asm volatile(
        "mma.sync.aligned.m16n8k16.row.col.f32.bf16.bf16.f32 "
        "{%0,%1,%2,%3}, {%4,%5,%6,%7}, {%8,%9}, {%0,%1,%2,%3};"
        : "+f"(c[0]), "+f"(c[1]), "+f"(c[2]), "+f"(c[3])
        : "r"(a[0]), "r"(a[1]), "r"(a[2]), "r"(a[3]), "r"(b0), "r"(b1));
}

__device__ __forceinline__ float sigmoidf_(float v) { return 1.0f / (1.0f + expf(-v)); }

// ---------------- staging: one B K-chunk (act hi/lo), swizzled ----------------
__device__ __forceinline__ void stage_b(int tid, int t, int c, uint32_t buf) {
    #pragma unroll
    for (int i = 0; i < 2; i++) {
        int idx = tid + i * TPB;            // 0..511
        int b = idx >> 3, q = idx & 7;
        uint32_t d = (uint32_t)(b * 128 + ((q * 16) ^ ((b & 7) << 4)));
        const __nv_bfloat16 *sh, *sl;
        if (c < 4) {
            size_t o = ((size_t)b * Tsz + t) * Isz + c * 64 + q * 8;
            sh = g_xh + o; sl = g_xl + o;
        } else {
            size_t o = (size_t)b * Hsz + (c - 4) * 64 + q * 8;
            sh = g_hh[t & 1] + o; sl = g_hl[t & 1] + o;
        }
        cp16(buf + d, sh);
        cp16(buf + BLHALF + d, sl);
    }
}

// ---------------- persistent LSTM kernel (final FC folded in) ----------------
__global__ void __launch_bounds__(TPB, 1)
lstm_persist(const float* __restrict__ fcW, const float* __restrict__ fcb,
             float* __restrict__ out)
{
    extern __shared__ __align__(16) char sm[];
    const uint32_t smu = smem_u32(sm);
    float* exch = (float*)(sm + BOFF);       // aliases B ring (safe by sync order)

    const int tid = threadIdx.x;
    const int cta = blockIdx.x;
    const int w = tid >> 5, lane = tid & 31;
    const int kg = w >> 2;                   // chunk parity group
    const int m0 = (w & 1) * 16;
    const int n0 = ((w >> 1) & 1) * 32;

    // ldsm lane constants (swizzled): addr = tile + row*128 + ((ks*32+sel)^xrow)
    const int aRow = m0 + (lane & 15);
    const uint32_t aRB  = (uint32_t)(aRow * 128);
    const uint32_t aX   = (uint32_t)((aRow & 7) << 4);
    const uint32_t aSel = (lane & 16) ? 16u : 0u;
    const int bRow = n0 + (lane & 7) + ((lane & 16) ? 8 : 0);
    const uint32_t bRB  = (uint32_t)(bRow * 128);
    const uint32_t bX   = (uint32_t)((bRow & 7) << 4);
    const uint32_t bSel = (lane & 8) ? 16u : 0u;

    // epilogue frag mapping
    const int er = m0 + (lane >> 2);
    const int ecol = 2 * (lane & 3);

    // pointwise mapping: 2 cells (pb, pj0..pj0+1)
    const int pb = tid & 63;
    const int pj0 = (tid >> 6) * 2;
    float bias_pw[2][4];
    #pragma unroll
    for (int i = 0; i < 2; i++)
        #pragma unroll
        for (int g = 0; g < 4; g++)
            bias_pw[i][g] = g_bsum[cta * 32 + g * 8 + pj0 + i];
    float c_reg[2] = {0.0f, 0.0f};

    // ---- stage resident W once (swizzled): 10240 cp16 ----
    {
        const __nv_bfloat16* wh = g_WrH + (size_t)cta * 32 * 1280;
        const __nv_bfloat16* wl = g_WrL + (size_t)cta * 32 * 1280;
        #pragma unroll
        for (int i = 0; i < 40; i++) {
            int idx = tid + i * TPB;          // 0..10239
            int c   = idx >> 9;
            int rem = idx & 511;
            int half = rem >> 8;
            int row  = (rem >> 3) & 31;
            int q    = rem & 7;
            size_t so = (size_t)row * 1280 + c * 64 + q * 8;
            uint32_t d = smu + (uint32_t)(c * ACH + half * AHALF
                         + row * 128 + ((q * 16) ^ ((row & 7) << 4)));
            cp16(d, (half ? wl : wh) + so);
        }
        CP_COMMIT();
    }

    // pre-stage x chunks 0..2 for t=0
    #pragma unroll
    for (int p = 0; p < 3; p++) {
        stage_b(tid, 0, p, smu + BOFF + (uint32_t)(p * BBUF));
        CP_COMMIT();
    }

    for (int t = 0; t < Tsz; t++) {
        float acc[4][4];
        #pragma unroll
        for (int nt = 0; nt < 4; nt++)
            #pragma unroll
            for (int i = 0; i < 4; i++) acc[nt][i] = 0.0f;

        for (int c = 0; c < NCHK; c++) {
            if (c <= 17)      CP_WAIT(2);
            else if (c == 18) CP_WAIT(1);
            else              CP_WAIT(0);
            __syncthreads();
            if (c + 3 < NCHK) {
                stage_b(tid, t, c + 3, smu + BOFF + (uint32_t)(((c + 3) & 3) * BBUF));
                CP_COMMIT();
            }
            if ((c & 1) == kg) {
                const uint32_t at = smu + (uint32_t)(c * ACH);
                const uint32_t bt = smu + BOFF + (uint32_t)((c & 3) * BBUF);
                #pragma unroll
                for (int ks = 0; ks < 4; ks++) {
                    const uint32_t ak = ((uint32_t)(ks * 32) + aSel) ^ aX;
                    const uint32_t bk = ((uint32_t)(ks * 32) + bSel) ^ bX;
                    uint32_t ah[4], al[4], bh0[4], bh1[4], bl0[4], bl1[4];
                    ldsm4(ah,  at + aRB + ak);
                    ldsm4(al,  at + AHALF + aRB + ak);
                    ldsm4(bh0, bt + bRB + bk);
                    ldsm4(bh1, bt + 2048 + bRB + bk);
                    ldsm4(bl0, bt + BLHALF + bRB + bk);
                    ldsm4(bl1, bt + BLHALF + 2048 + bRB + bk);
                    mma16816(acc[0], ah, bh0[0], bh0[1]);
                    mma16816(acc[1], ah, bh0[2], bh0[3]);
                    mma16816(acc[2], ah, bh1[0], bh1[1]);
                    mma16816(acc[3], ah, bh1[2], bh1[3]);
                    mma16816(acc[0], ah, bl0[0], bl0[1]);
                    mma16816(acc[1], ah, bl0[2], bl0[3]);
                    mma16816(acc[2], ah, bl1[0], bl1[1]);
                    mma16816(acc[3], ah, bl1[2], bl1[3]);
                    mma16816(acc[0], al, bh0[0], bh0[1]);
                    mma16816(acc[1], al, bh0[2], bh0[3]);
                    mma16816(acc[2], al, bh1[0], bh1[1]);
                    mma16816(acc[3], al, bh1[2], bh1[3]);
                }
            }
        }
        __syncthreads();   // all computes done before exch write (aliases B bufs)

        // ---- exchange: each kg writes its partial region ----
        {
            float* ex = exch + kg * (32 * EXST);
            #pragma unroll
            for (int nt = 0; nt < 4; nt++) {
                int col = n0 + nt * 8 + ecol;
                ex[er * EXST + col]           = acc[nt][0];
                ex[er * EXST + col + 1]       = acc[nt][1];
                ex[(er + 8) * EXST + col]     = acc[nt][2];
                ex[(er + 8) * EXST + col + 1] = acc[nt][3];
            }
        }
        __syncthreads();

        // ---- pointwise LSTM update ----
        __nv_bfloat16* hho = g_hh[(t + 1) & 1];
        __nv_bfloat16* hlo = g_hl[(t + 1) & 1];
        float hn2[2];
        #pragma unroll
        for (int i = 0; i < 2; i++) {
            int jj = pj0 + i;
            float gv[4];
            #pragma unroll
            for (int g = 0; g < 4; g++) {
                int row = g * 8 + jj;
                gv[g] = exch[row * EXST + pb] + exch[32 * EXST + row * EXST + pb]
                        + bias_pw[i][g];
            }
            float ig = sigmoidf_(gv[0]);
            float fg = sigmoidf_(gv[1]);
            float gg = tanhf(gv[2]);
            float og = sigmoidf_(gv[3]);
            float cn = fg * c_reg[i] + ig * gg;
            c_reg[i] = cn;
            hn2[i] = og * tanhf(cn);
        }
        {
            int off = pb * Hsz + cta * 8 + pj0;     // even → 4B aligned
            __nv_bfloat16 h0 = __float2bfloat16(hn2[0]);
            __nv_bfloat16 h1 = __float2bfloat16(hn2[1]);
            *(__nv_bfloat162*)(hho + off) = __nv_bfloat162(h0, h1);
            *(__nv_bfloat162*)(hlo + off) = __nv_bfloat162(
                __float2bfloat16(hn2[0] - __bfloat162float(h0)),
                __float2bfloat16(hn2[1] - __bfloat162float(h1)));
            if (t == Tsz - 1) {
                g_hf[off]     = hn2[0];
                g_hf[off + 1] = hn2[1];
            }
        }

        __threadfence();
        __syncthreads();   // pointwise exch reads done -> pre-stage may clobber

        // pre-stage x chunks 0..2 for t+1 (overlaps barrier wait)
        if (t + 1 < Tsz) {
            #pragma unroll
            for (int p = 0; p < 3; p++) {
                stage_b(tid, t + 1, p, smu + BOFF + (uint32_t)(p * BBUF));
                CP_COMMIT();
            }
        }

        // ---- grid barrier ----
        if (tid == 0) {
            atomicAdd(&g_cnt, 1u);
            unsigned bound = (unsigned)(t + 1) * NCTA;
            while (*(volatile unsigned*)&g_cnt < bound) { }
            __threadfence();
        }
        __syncthreads();
    }

    // ---- final FC: CTA b < 64 computes out[b] ----
    if (cta < Bsz) {
        float s = 0.0f;
        for (int j = tid; j < Hsz; j += TPB)
            s += tanhf(g_hf[cta * Hsz + j]) * fcW[j];
        #pragma unroll
        for (int d = 16; d > 0; d >>= 1)
            s += __shfl_xor_sync(0xFFFFFFFFu, s, d);
        __shared__ float red[8];
        if (lane == 0) red[w] = s;
        __syncthreads();
        if (tid == 0) {
            float tot = 0.0f;
            #pragma unroll
            for (int i = 0; i < 8; i++) tot += red[i];
            out[cta] = tot + fcb[0];
        }
    }
}

// ---------------- fused prep kernel ----------------
#define PREP_W_BLKS 20480
#define PREP_X_BLKS 32768
#define PREP_B_BLKS 16
#define PREP_I_BLKS 256
#define PREP_GRID (PREP_W_BLKS + PREP_X_BLKS + PREP_B_BLKS + PREP_I_BLKS)

__global__ void prep_kernel(const float* __restrict__ x,
                            const float* __restrict__ Wih,
                            const float* __restrict__ Whh,
                            const float* __restrict__ bih,
                            const float* __restrict__ bhh)
{
    int bid = blockIdx.x;
    int tid = threadIdx.x;
    if (bid < PREP_W_BLKS) {
        int idx = bid * 256 + tid;
        int k  = idx % 1280;
        int rr = idx / 1280;
        int row = rr & 31, cta = rr >> 5;
        int gate = row >> 3, jj = row & 7;
        int R = gate * Hsz + cta * 8 + jj;
        float v = (k < Isz) ? Wih[(size_t)R * Isz + k]
                            : Whh[(size_t)R * Hsz + (k - Isz)];
        __nv_bfloat16 hi = __float2bfloat16(v);
        g_WrH[idx] = hi;
        g_WrL[idx] = __float2bfloat16(v - __bfloat162float(hi));
    } else if (bid < PREP_W_BLKS + PREP_X_BLKS) {
        size_t idx = (size_t)(bid - PREP_W_BLKS) * 256 + tid;
        float v = x[idx];
        __nv_bfloat16 hi = __float2bfloat16(v);
        g_xh[idx] = hi;
        g_xl[idx] = __float2bfloat16(v - __bfloat162float(hi));
    } else if (bid < PREP_W_BLKS + PREP_X_BLKS + PREP_B_BLKS) {
        int idx = (bid - PREP_W_BLKS - PREP_X_BLKS) * 256 + tid;
        int row = idx & 31, cta = idx >> 5;
        int gate = row >> 3, jj = row & 7;
        int R = gate * Hsz + cta * 8 + jj;
        g_bsum[idx] = bih[R] + bhh[R];
    } else {
        int i = (bid - PREP_W_BLKS - PREP_X_BLKS - PREP_B_BLKS) * 256 + tid;
        g_hh[0][i] = __float2bfloat16(0.0f);
        g_hl[0][i] = __float2bfloat16(0.0f);
        if (i == 0) g_cnt = 0u;
    }
}

extern "C" void kernel_launch(void* const* d_in, const int* in_sizes, int n_in,
                              void* d_out, int out_size)
{
    (void)in_sizes; (void)n_in; (void)out_size;
    const float* x   = (const float*)d_in[0];
    const float* Wih = (const float*)d_in[1];
    const float* Whh = (const float*)d_in[2];
    const float* bih = (const float*)d_in[3];
    const float* bhh = (const float*)d_in[4];
    const float* fcW = (const float*)d_in[5];
    const float* fcb = (const float*)d_in[6];
    float* out = (float*)d_out;

    cudaFuncSetAttribute(lstm_persist,
                         cudaFuncAttributeMaxDynamicSharedMemorySize, SMEM_DYN);

    prep_kernel<<<PREP_GRID, 256>>>(x, Wih, Whh, bih, bhh);
    lstm_persist<<<NCTA, TPB, SMEM_DYN>>>(fcW, fcb, out);
}